// round 14
// baseline (speedup 1.0000x reference)
#include <cuda_runtime.h>
#include <cuda_fp16.h>
#include <math.h>
#include <stdint.h>

// Shapes (fixed by the problem)
#define BB 128
#define SS 1000
#define HH 256
#define SP 1024

// ---------------- scratch (device globals; no allocations allowed) ----------
__device__ float g_bias_attn[BB * 768];
__device__ float g_scores[BB * SP];
__device__ float g_bias_dec[BB * 512];
__device__ float g_oscores[BB * SP];
// Weights as single fp16, K-packed rows
__device__ __half g_Wh_a[768 * 512];
__device__ __half g_Wh_d[512 * 256];
// Activations as single fp16: [b][s][k]
__device__ __half g_A16_s[BB * SS * HH];
__device__ __half g_A16_d[BB * SS * HH];

// ============================================================================
// Baseline-PTX helpers (compile under compute_103: mma.sync / ldmatrix / cp.async)
// ============================================================================
__device__ __forceinline__ uint32_t smem_u32(const void* p) {
    uint32_t a;
    asm("{ .reg .u64 t; cvta.to.shared.u64 t, %1; cvt.u32.u64 %0, t; }" : "=r"(a) : "l"(p));
    return a;
}
__device__ __forceinline__ void ldm4(uint32_t* r, uint32_t addr) {
    asm volatile("ldmatrix.sync.aligned.m8n8.x4.shared.b16 {%0,%1,%2,%3}, [%4];"
                 : "=r"(r[0]), "=r"(r[1]), "=r"(r[2]), "=r"(r[3]) : "r"(addr));
}
__device__ __forceinline__ void mma_f16(float* c, const uint32_t* a, uint32_t b0, uint32_t b1) {
    asm volatile("mma.sync.aligned.m16n8k16.row.col.f32.f16.f16.f32 "
                 "{%0,%1,%2,%3}, {%4,%5,%6,%7}, {%8,%9}, {%0,%1,%2,%3};"
                 : "+f"(c[0]), "+f"(c[1]), "+f"(c[2]), "+f"(c[3])
                 : "r"(a[0]), "r"(a[1]), "r"(a[2]), "r"(a[3]), "r"(b0), "r"(b1));
}
__device__ __forceinline__ void cpa16(uint32_t dst, const void* src) {
    asm volatile("cp.async.cg.shared.global [%0], [%1], 16;" :: "r"(dst), "l"(src));
}
#define CP_COMMIT() asm volatile("cp.async.commit_group;" ::: "memory")
#define CP_WAIT1()  asm volatile("cp.async.wait_group 1;" ::: "memory")
// MUFU-based tanh (sm_75+ baseline PTX), max err ~2^-10.66
__device__ __forceinline__ float tanha(float x) {
    float y;
    asm("tanh.approx.f32 %0, %1;" : "=f"(y) : "f"(x));
    return y;
}

// ============================================================================
// Fused prologue kernel: gru (128 blocks) + prep_w (2048) + prep_a (64000).
// All three are independent; one launch lets the small work hide under
// prep_a's bandwidth-bound sweep and removes two launch gaps.
// ============================================================================
#define NB_GRU   BB
#define NB_PREPW (((768 * 512 + 512 * 256) + 255) / 256)                // 2048
#define NB_PREPA ((int)(((long)2 * BB * SS * HH / 4 + 255) / 256))      // 64000

__device__ void do_gru(int b, int t,
                       const float* __restrict__ din, const float* __restrict__ lasth,
                       const float* __restrict__ embW, const float* __restrict__ embb,
                       const float* __restrict__ Wih, const float* __restrict__ Whh,
                       const float* __restrict__ bih, const float* __restrict__ bhh,
                       const float* __restrict__ attnW, float* __restrict__ hid_out,
                       int write_hidden, float* smem3) {
    float* emb  = smem3;
    float* hold = smem3 + HH;
    float* hnew = smem3 + 2 * HH;

    const float d0 = din[b * 2 + 0];
    const float d1 = din[b * 2 + 1];
    emb[t]  = d0 * embW[t * 2 + 0] + d1 * embW[t * 2 + 1] + embb[t];
    hold[t] = lasth[b * HH + t];
    __syncthreads();

    float gx[3], gh[3];
#pragma unroll
    for (int g = 0; g < 3; g++) { gx[g] = bih[g * HH + t]; gh[g] = bhh[g * HH + t]; }
#pragma unroll
    for (int g = 0; g < 3; g++) {
        const float4* wi = reinterpret_cast<const float4*>(Wih + (g * HH + t) * HH);
        const float4* wh = reinterpret_cast<const float4*>(Whh + (g * HH + t) * HH);
        const float4* ev = reinterpret_cast<const float4*>(emb);
        const float4* hv = reinterpret_cast<const float4*>(hold);
        float sx = 0.f, sh = 0.f;
#pragma unroll 4
        for (int k = 0; k < HH / 4; k++) {
            float4 a = wi[k], c = wh[k], e = ev[k], h4 = hv[k];
            sx += a.x * e.x + a.y * e.y + a.z * e.z + a.w * e.w;
            sh += c.x * h4.x + c.y * h4.y + c.z * h4.z + c.w * h4.w;
        }
        gx[g] += sx; gh[g] += sh;
    }

    const float r = 1.f / (1.f + expf(-(gx[0] + gh[0])));
    const float z = 1.f / (1.f + expf(-(gx[1] + gh[1])));
    const float n = tanhf(gx[2] + r * gh[2]);
    const float hv = (1.f - z) * n + z * hold[t];
    hnew[t] = hv;
    if (write_hidden) hid_out[b * HH + t] = hv;
    __syncthreads();

    const float4* hv4 = reinterpret_cast<const float4*>(hnew);
#pragma unroll
    for (int g = 0; g < 3; g++) {
        const int j = g * HH + t;
        const float4* w = reinterpret_cast<const float4*>(attnW + j * 768 + 512);
        float s = 0.f;
#pragma unroll 4
        for (int k = 0; k < HH / 4; k++) {
            float4 ww = w[k], hh = hv4[k];
            s += ww.x * hh.x + ww.y * hh.y + ww.z * hh.z + ww.w * hh.w;
        }
        g_bias_attn[b * 768 + j] = s;
    }
}

__global__ __launch_bounds__(256) void k_prep_all(
    const float* __restrict__ din, const float* __restrict__ lasth,
    const float* __restrict__ statp, const float* __restrict__ dynp,
    const float* __restrict__ embW, const float* __restrict__ embb,
    const float* __restrict__ Wih, const float* __restrict__ Whh,
    const float* __restrict__ bih, const float* __restrict__ bhh,
    const float* __restrict__ attnW, const float* __restrict__ decW,
    float* __restrict__ hid_out, int write_hidden) {
    __shared__ __align__(16) float smem3[3 * HH];
    const int blk = blockIdx.x;
    const int t = threadIdx.x;

    if (blk < NB_GRU) {
        do_gru(blk, t, din, lasth, embW, embb, Wih, Whh, bih, bhh, attnW,
               hid_out, write_hidden, smem3);
        return;
    }
    if (blk < NB_GRU + NB_PREPW) {
        const int i = (blk - NB_GRU) * 256 + t;
        if (i < 768 * 512) {
            const int j = i >> 9, k = i & 511;
            g_Wh_a[i] = __float2half_rn(attnW[j * 768 + k]);
        } else {
            const int q = i - 768 * 512;
            const int j = q >> 8, k = q & 255;
            g_Wh_d[q] = __float2half_rn(decW[j * 512 + k]);
        }
        return;
    }
    // prep_a
    const long E4 = (long)BB * SS * HH / 4;
    const long i = (long)(blk - NB_GRU - NB_PREPW) * 256 + t;
    if (i >= 2 * E4) return;
    const bool dyn = (i >= E4);
    const long j = dyn ? i - E4 : i;
    const float4 x = reinterpret_cast<const float4*>(dyn ? dynp : statp)[j];
    __half2 lo = __floats2half2_rn(x.x, x.y);
    __half2 hi = __floats2half2_rn(x.z, x.w);
    uint2* dst = reinterpret_cast<uint2*>(dyn ? g_A16_d : g_A16_s);
    dst[j] = make_uint2(*(const unsigned*)&lo, *(const unsigned*)&hi);
}

// ============================================================================
// Kernel 2/4: fused score GEMM on HMMA (single fp16 term, fp32 accum)
//   score[b,s] = sum_j v[j] * tanh( sum_k A[b,s,k]*W[j,k] + bias[b,j] )
// R12 config: block 128 rows x full N, 8 warps = 4(M) x 2(N), warp tile
// 32x64, K chunks of 64, 3-buffer/2-prefetch pipeline with ONE barrier per
// chunk, MUFU tanh epilogue.  smem 111.6KB -> 2 CTAs/SM, regs 128.
// ============================================================================
#define KCH   64
#define TSTR  72
#define TILE_B (128 * TSTR * 2)   // 18432 bytes
#define A_OFF  0
#define W_OFF  TILE_B
#define BUF_B  (2 * TILE_B)       // 36864 bytes
#define SMEM_GEMM (3 * BUF_B + 1024)

template <int K, int N>
__global__ __launch_bounds__(256, 2) void k_gemm(
    const __half* __restrict__ A16_s, const __half* __restrict__ A16_d,
    const __half* __restrict__ Wh,
    const float* __restrict__ bias, const float* __restrict__ v,
    float* __restrict__ scores) {
    constexpr int KC = K / KCH;     // 8 or 4
    constexpr int NT = N / 128;     // 6 or 4
    constexpr int NC = NT * KC;

    extern __shared__ char sm[];
    const uint32_t su = smem_u32(sm);
    float* sred = (float*)(sm + 3 * BUF_B);

    const int tid = threadIdx.x, lane = tid & 31, wid = tid >> 5;
    const int wm = wid & 3, wn = wid >> 2;
    const int b = blockIdx.y, s0 = blockIdx.x * 128;

    // cp.async: thread covers (row = tid/2, 32-elem half = tid&1); 4x16B each
    const int cr = tid >> 1, ch = tid & 1;
    const long abase = ((long)b * SS + min(s0 + cr, SS - 1)) * HH + ch * 32;
    const uint32_t cd = (uint32_t)((cr * TSTR + ch * 32) * 2);

    auto issue = [&](int c) {
        if (c < NC) {
            const int nt = c / KC, kc = c - nt * KC;
            const __half* asrc;
            int kofs;
            if (K == 512 && kc >= 4) { asrc = A16_d; kofs = (kc - 4) * KCH; }
            else                     { asrc = A16_s; kofs = kc * KCH; }
            const __half* pa = asrc + abase + kofs;
            const long wrow = (long)(nt * 128 + cr) * K + kc * KCH + ch * 32;
            const uint32_t d = su + (uint32_t)(c % 3) * BUF_B + cd;
#pragma unroll
            for (int q = 0; q < 4; q++) {
                cpa16(d + A_OFF + q * 16, pa + q * 8);
                cpa16(d + W_OFF + q * 16, Wh + wrow + q * 8);
            }
        }
    };

    // ldmatrix per-thread base offsets (bytes), within a buffer
    const uint32_t a_sm = (uint32_t)((wm * 32 + (lane & 15)) * (TSTR * 2) + ((lane >> 4) & 1) * 16);
    const uint32_t w_sm = (uint32_t)((wn * 64 + (lane & 7) + ((lane & 16) >> 1)) * (TSTR * 2) + (lane & 8) * 2);

    float part[4] = {0.f, 0.f, 0.f, 0.f};

    issue(0); CP_COMMIT();
    issue(1); CP_COMMIT();

    float acc[2][8][4];

    for (int c = 0; c < NC; c++) {
        const int kc = c % KC;
        const int nt = c / KC;
        if (kc == 0) {
#pragma unroll
            for (int i = 0; i < 2; i++)
#pragma unroll
                for (int j = 0; j < 8; j++)
#pragma unroll
                    for (int q = 0; q < 4; q++) acc[i][j][q] = 0.f;
        }

        CP_WAIT1();          // group c landed (group c+1 may be in flight)
        __syncthreads();     // all warps done reading buf (c-1)%3 + visibility
        issue(c + 2);        // refill buf (c+2)%3 == (c-1)%3
        CP_COMMIT();

        const uint32_t bo = su + (uint32_t)(c % 3) * BUF_B;
#pragma unroll
        for (int ks = 0; ks < 4; ks++) {
            const uint32_t ko = (uint32_t)(ks * 32);  // 16 elems * 2B
            uint32_t af[2][4];
#pragma unroll
            for (int mi = 0; mi < 2; mi++)
                ldm4(af[mi], bo + A_OFF + a_sm + (uint32_t)(mi * 16 * TSTR * 2) + ko);
#pragma unroll
            for (int ng = 0; ng < 4; ng++) {
                uint32_t wf[4];
                ldm4(wf, bo + W_OFF + w_sm + (uint32_t)(ng * 16 * TSTR * 2) + ko);
#pragma unroll
                for (int mi = 0; mi < 2; mi++) {
                    mma_f16(acc[mi][2 * ng],     af[mi], wf[0], wf[1]);
                    mma_f16(acc[mi][2 * ng + 1], af[mi], wf[2], wf[3]);
                }
            }
        }

        if (kc == KC - 1) {
            // ---- epilogue for this N tile: tanh + v-dot, register-only ----
            const int jb = nt * 128 + wn * 64 + 2 * (lane & 3);
#pragma unroll
            for (int n8 = 0; n8 < 8; n8++) {
                const int j = jb + n8 * 8;
                const float2 bv = *reinterpret_cast<const float2*>(&bias[(long)b * N + j]);
                const float2 vv = *reinterpret_cast<const float2*>(&v[j]);
#pragma unroll
                for (int mi = 0; mi < 2; mi++) {
                    part[mi * 2 + 0] += vv.x * tanha(acc[mi][n8][0] + bv.x)
                                      + vv.y * tanha(acc[mi][n8][1] + bv.y);
                    part[mi * 2 + 1] += vv.x * tanha(acc[mi][n8][2] + bv.x)
                                      + vv.y * tanha(acc[mi][n8][3] + bv.y);
                }
            }
        }
    }

    // reduce across the 4 lanes sharing a row (lane bits 0,1)
#pragma unroll
    for (int i = 0; i < 4; i++) {
        part[i] += __shfl_xor_sync(0xffffffffu, part[i], 1);
        part[i] += __shfl_xor_sync(0xffffffffu, part[i], 2);
    }
    if ((lane & 3) == 0) {
        const int r = lane >> 2;
        const int base = wn * 128 + wm * 32;
        sred[base + r]      = part[0];
        sred[base + r + 8]  = part[1];
        sred[base + r + 16] = part[2];
        sred[base + r + 24] = part[3];
    }
    __syncthreads();
    if (tid < 128) {
        const int s = s0 + tid;
        if (s < SS) scores[b * SP + s] = sred[tid] + sred[128 + tid];
    }
}

// ============================================================================
// Kernel 3: softmax(scores) -> context (fp16 static, ALL 256 threads) -> bias_dec
// ============================================================================
__global__ __launch_bounds__(256) void k_ctx(
    const __half* __restrict__ A16_s, const float* __restrict__ decW) {
    const int b = blockIdx.x;
    const int t = threadIdx.x;

    __shared__ float attn[SP];
    __shared__ float red[256];
    __shared__ __align__(16) float ctx[HH];
    __shared__ float ctx2[2][HH];

    float m = -1e30f;
    for (int s = t; s < SS; s += 256) m = fmaxf(m, g_scores[b * SP + s]);
    red[t] = m; __syncthreads();
    for (int o = 128; o; o >>= 1) { if (t < o) red[t] = fmaxf(red[t], red[t + o]); __syncthreads(); }
    m = red[0]; __syncthreads();

    float lsum = 0.f;
    for (int s = t; s < SS; s += 256) {
        const float e = __expf(g_scores[b * SP + s] - m);
        attn[s] = e; lsum += e;
    }
    red[t] = lsum; __syncthreads();
    for (int o = 128; o; o >>= 1) { if (t < o) red[t] += red[t + o]; __syncthreads(); }
    const float inv = 1.f / red[0];
    __syncthreads();

    // context with all 256 threads: tt = h-pair index, sh2 = s parity
    {
        const int tt = t & 127, sh2 = t >> 7;
        const __half2* sp = reinterpret_cast<const __half2*>(A16_s + (long)b * SS * HH) + tt;
        float c0 = 0.f, c1 = 0.f;
        for (int s = sh2; s < SS; s += 2) {
            const float2 v0 = __half22float2(sp[s * (HH / 2)]);
            c0 += attn[s] * v0.x;
            c1 += attn[s] * v0.y;
        }
        ctx2[sh2][2 * tt]     = c0;
        ctx2[sh2][2 * tt + 1] = c1;
    }
    __syncthreads();
    if (t < HH) ctx[t] = (ctx2[0][t] + ctx2[1][t]) * inv;
    __syncthreads();

    const float4* cv = reinterpret_cast<const float4*>(ctx);
#pragma unroll
    for (int g = 0; g < 2; g++) {
        const int j = g * HH + t;
        const float4* w = reinterpret_cast<const float4*>(decW + j * 512 + 256);
        float sacc = 0.f;
#pragma unroll 4
        for (int k = 0; k < HH / 4; k++) {
            float4 ww = w[k], cc = cv[k];
            sacc += ww.x * cc.x + ww.y * cc.y + ww.z * cc.z + ww.w * cc.w;
        }
        g_bias_dec[b * 512 + j] = sacc;
    }
}

// ============================================================================
// Kernel 5: final softmax -> outputs [B,S]
// ============================================================================
__global__ __launch_bounds__(256) void k_softmax_out(float* __restrict__ out) {
    const int b = blockIdx.x;
    const int t = threadIdx.x;
    __shared__ float e_s[SP];
    __shared__ float red[256];

    float m = -1e30f;
    for (int s = t; s < SS; s += 256) m = fmaxf(m, g_oscores[b * SP + s]);
    red[t] = m; __syncthreads();
    for (int o = 128; o; o >>= 1) { if (t < o) red[t] = fmaxf(red[t], red[t + o]); __syncthreads(); }
    m = red[0]; __syncthreads();

    float lsum = 0.f;
    for (int s = t; s < SS; s += 256) {
        const float e = __expf(g_oscores[b * SP + s] - m);
        e_s[s] = e; lsum += e;
    }
    red[t] = lsum; __syncthreads();
    for (int o = 128; o; o >>= 1) { if (t < o) red[t] += red[t + o]; __syncthreads(); }
    const float inv = 1.f / red[0];
    __syncthreads();

    for (int s = t; s < SS; s += 256) out[b * SS + s] = e_s[s] * inv;
}

// ============================================================================
// Launch
// ============================================================================
extern "C" void kernel_launch(void* const* d_in, const int* in_sizes, int n_in,
                              void* d_out, int out_size) {
    const float* din   = (const float*)d_in[0];
    const float* lasth = (const float*)d_in[1];
    const float* statp = (const float*)d_in[2];
    const float* dynp  = (const float*)d_in[3];
    const float* embW  = (const float*)d_in[4];
    const float* embb  = (const float*)d_in[5];
    const float* Wih   = (const float*)d_in[6];
    const float* Whh   = (const float*)d_in[7];
    const float* bih   = (const float*)d_in[8];
    const float* bhh   = (const float*)d_in[9];
    const float* attnW = (const float*)d_in[10];
    const float* attnv = (const float*)d_in[11];
    const float* decW  = (const float*)d_in[12];
    const float* decv  = (const float*)d_in[13];
    float* out = (float*)d_out;

    const int write_hidden = (out_size >= BB * SS + BB * HH) ? 1 : 0;
    float* hid_out = out + BB * SS;

    float *p_bias_attn, *p_scores, *p_bias_dec, *p_oscores;
    __half *pWh_a, *pWh_d, *pA16_s, *pA16_d;
    cudaGetSymbolAddress((void**)&p_bias_attn, g_bias_attn);
    cudaGetSymbolAddress((void**)&p_scores,    g_scores);
    cudaGetSymbolAddress((void**)&p_bias_dec,  g_bias_dec);
    cudaGetSymbolAddress((void**)&p_oscores,   g_oscores);
    cudaGetSymbolAddress((void**)&pWh_a, g_Wh_a);
    cudaGetSymbolAddress((void**)&pWh_d, g_Wh_d);
    cudaGetSymbolAddress((void**)&pA16_s, g_A16_s);
    cudaGetSymbolAddress((void**)&pA16_d, g_A16_d);

    cudaFuncSetAttribute(k_gemm<512, 768>, cudaFuncAttributeMaxDynamicSharedMemorySize, SMEM_GEMM);
    cudaFuncSetAttribute(k_gemm<256, 512>, cudaFuncAttributeMaxDynamicSharedMemorySize, SMEM_GEMM);

    const int prep_blocks = NB_GRU + NB_PREPW + NB_PREPA;
    k_prep_all<<<prep_blocks, 256>>>(din, lasth, statp, dynp, embW, embb,
                                     Wih, Whh, bih, bhh, attnW, decW,
                                     hid_out, write_hidden);

    dim3 g(8, BB);  // 8 M-tiles of 128 rows, 128 batches
    k_gemm<512, 768><<<g, 256, SMEM_GEMM>>>(pA16_s, pA16_d,
                                            pWh_a, p_bias_attn, attnv, p_scores);

    k_ctx<<<BB, 256>>>(pA16_s, decW);

    k_gemm<256, 512><<<g, 256, SMEM_GEMM>>>(pA16_s, pA16_s,
                                            pWh_d, p_bias_dec, decv, p_oscores);

    k_softmax_out<<<BB, 256>>>(out);
}

// round 15
// speedup vs baseline: 1.0320x; 1.0320x over previous
#include <cuda_runtime.h>
#include <cuda_fp16.h>
#include <math.h>
#include <stdint.h>

// Shapes (fixed by the problem)
#define BB 128
#define SS 1000
#define HH 256
#define SP 1024

// ---------------- scratch (device globals; no allocations allowed) ----------
__device__ float g_bias_attn[BB * 768];
__device__ float g_scores[BB * SP];
__device__ float g_bias_dec[BB * 512];
__device__ float g_oscores[BB * SP];
// Weights as single fp16, K-packed rows
__device__ __half g_Wh_a[768 * 512];
__device__ __half g_Wh_d[512 * 256];
// Activations as single fp16: [b][s][k]
__device__ __half g_A16_s[BB * SS * HH];
__device__ __half g_A16_d[BB * SS * HH];

// ============================================================================
// Baseline-PTX helpers (compile under compute_103: mma.sync / ldmatrix / cp.async)
// ============================================================================
__device__ __forceinline__ uint32_t smem_u32(const void* p) {
    uint32_t a;
    asm("{ .reg .u64 t; cvta.to.shared.u64 t, %1; cvt.u32.u64 %0, t; }" : "=r"(a) : "l"(p));
    return a;
}
__device__ __forceinline__ void ldm4(uint32_t* r, uint32_t addr) {
    asm volatile("ldmatrix.sync.aligned.m8n8.x4.shared.b16 {%0,%1,%2,%3}, [%4];"
                 : "=r"(r[0]), "=r"(r[1]), "=r"(r[2]), "=r"(r[3]) : "r"(addr));
}
__device__ __forceinline__ void mma_f16(float* c, const uint32_t* a, uint32_t b0, uint32_t b1) {
    asm volatile("mma.sync.aligned.m16n8k16.row.col.f32.f16.f16.f32 "
                 "{%0,%1,%2,%3}, {%4,%5,%6,%7}, {%8,%9}, {%0,%1,%2,%3};"
                 : "+f"(c[0]), "+f"(c[1]), "+f"(c[2]), "+f"(c[3])
                 : "r"(a[0]), "r"(a[1]), "r"(a[2]), "r"(a[3]), "r"(b0), "r"(b1));
}
__device__ __forceinline__ void cpa16(uint32_t dst, const void* src) {
    asm volatile("cp.async.cg.shared.global [%0], [%1], 16;" :: "r"(dst), "l"(src));
}
#define CP_COMMIT() asm volatile("cp.async.commit_group;" ::: "memory")
#define CP_WAIT1()  asm volatile("cp.async.wait_group 1;" ::: "memory")
// MUFU-based tanh (sm_75+ baseline PTX), max err ~2^-10.66
__device__ __forceinline__ float tanha(float x) {
    float y;
    asm("tanh.approx.f32 %0, %1;" : "=f"(y) : "f"(x));
    return y;
}

// ============================================================================
// Kernel 0: fused weight+activation fp16 prep, FAT grid-stride blocks.
// 2368 CTAs (16/SM): W part ~0.9 iter/thread, A part ~27 float4 iters/thread.
// Purely bandwidth-bound (~393MB); kills the 64K-tiny-CTA scheduling overhead.
// ============================================================================
#define PREP_BLOCKS 2368

__global__ __launch_bounds__(256) void k_prep(
    const float* __restrict__ attnW, const float* __restrict__ decW,
    const float* __restrict__ statp, const float* __restrict__ dynp) {
    const long tid0 = (long)blockIdx.x * 256 + threadIdx.x;
    const long nthr = (long)PREP_BLOCKS * 256;

    // ---- weights (scalar grid-stride) ----
    const int WTOT = 768 * 512 + 512 * 256;
    for (long i = tid0; i < WTOT; i += nthr) {
        if (i < 768 * 512) {
            const int j = (int)(i >> 9), k = (int)(i & 511);
            g_Wh_a[i] = __float2half_rn(attnW[j * 768 + k]);
        } else {
            const int q = (int)(i - 768 * 512);
            const int j = q >> 8, k = q & 255;
            g_Wh_d[q] = __float2half_rn(decW[j * 512 + k]);
        }
    }

    // ---- activations (float4 grid-stride over static then dynamic) ----
    const long E4 = (long)BB * SS * HH / 4;
    for (long i = tid0; i < 2 * E4; i += nthr) {
        const bool dyn = (i >= E4);
        const long j = dyn ? i - E4 : i;
        const float4 x = reinterpret_cast<const float4*>(dyn ? dynp : statp)[j];
        __half2 lo = __floats2half2_rn(x.x, x.y);
        __half2 hi = __floats2half2_rn(x.z, x.w);
        uint2* dst = reinterpret_cast<uint2*>(dyn ? g_A16_d : g_A16_s);
        dst[j] = make_uint2(*(const unsigned*)&lo, *(const unsigned*)&hi);
    }
}

// ============================================================================
// Kernel 1: embed + GRU cell + bias_attn  (fp32)
// ============================================================================
__global__ __launch_bounds__(256) void k_gru(
    const float* __restrict__ din, const float* __restrict__ lasth,
    const float* __restrict__ embW, const float* __restrict__ embb,
    const float* __restrict__ Wih, const float* __restrict__ Whh,
    const float* __restrict__ bih, const float* __restrict__ bhh,
    const float* __restrict__ attnW, float* __restrict__ hid_out, int write_hidden) {
    const int b = blockIdx.x;
    const int t = threadIdx.x;

    __shared__ __align__(16) float emb[HH];
    __shared__ __align__(16) float hold[HH];
    __shared__ __align__(16) float hnew[HH];

    const float d0 = din[b * 2 + 0];
    const float d1 = din[b * 2 + 1];
    emb[t]  = d0 * embW[t * 2 + 0] + d1 * embW[t * 2 + 1] + embb[t];
    hold[t] = lasth[b * HH + t];
    __syncthreads();

    float gx[3], gh[3];
#pragma unroll
    for (int g = 0; g < 3; g++) { gx[g] = bih[g * HH + t]; gh[g] = bhh[g * HH + t]; }
#pragma unroll
    for (int g = 0; g < 3; g++) {
        const float4* wi = reinterpret_cast<const float4*>(Wih + (g * HH + t) * HH);
        const float4* wh = reinterpret_cast<const float4*>(Whh + (g * HH + t) * HH);
        const float4* ev = reinterpret_cast<const float4*>(emb);
        const float4* hv = reinterpret_cast<const float4*>(hold);
        float sx = 0.f, sh = 0.f;
#pragma unroll 4
        for (int k = 0; k < HH / 4; k++) {
            float4 a = wi[k], c = wh[k], e = ev[k], h4 = hv[k];
            sx += a.x * e.x + a.y * e.y + a.z * e.z + a.w * e.w;
            sh += c.x * h4.x + c.y * h4.y + c.z * h4.z + c.w * h4.w;
        }
        gx[g] += sx; gh[g] += sh;
    }

    const float r = 1.f / (1.f + expf(-(gx[0] + gh[0])));
    const float z = 1.f / (1.f + expf(-(gx[1] + gh[1])));
    const float n = tanhf(gx[2] + r * gh[2]);
    const float hv = (1.f - z) * n + z * hold[t];
    hnew[t] = hv;
    if (write_hidden) hid_out[b * HH + t] = hv;
    __syncthreads();

    const float4* hv4 = reinterpret_cast<const float4*>(hnew);
#pragma unroll
    for (int g = 0; g < 3; g++) {
        const int j = g * HH + t;
        const float4* w = reinterpret_cast<const float4*>(attnW + j * 768 + 512);
        float s = 0.f;
#pragma unroll 4
        for (int k = 0; k < HH / 4; k++) {
            float4 ww = w[k], hh = hv4[k];
            s += ww.x * hh.x + ww.y * hh.y + ww.z * hh.z + ww.w * hh.w;
        }
        g_bias_attn[b * 768 + j] = s;
    }
}

// ============================================================================
// Kernel 2/4: fused score GEMM on HMMA (single fp16 term, fp32 accum)
//   score[b,s] = sum_j v[j] * tanh( sum_k A[b,s,k]*W[j,k] + bias[b,j] )
// R12 config (best known): block 128 rows x full N, 8 warps = 4(M) x 2(N),
// warp tile 32x64, K chunks of 64, 3-buffer/2-prefetch cp.async pipeline with
// ONE barrier per chunk, MUFU tanh epilogue.  Row stride 72 fp16 (144B,
// conflict-free).  smem 111.6KB -> 2 CTAs/SM, regs 128 (regfile full).
// ============================================================================
#define KCH   64
#define TSTR  72
#define TILE_B (128 * TSTR * 2)   // 18432 bytes
#define A_OFF  0
#define W_OFF  TILE_B
#define BUF_B  (2 * TILE_B)       // 36864 bytes
#define SMEM_GEMM (3 * BUF_B + 1024)

template <int K, int N>
__global__ __launch_bounds__(256, 2) void k_gemm(
    const __half* __restrict__ A16_s, const __half* __restrict__ A16_d,
    const __half* __restrict__ Wh,
    const float* __restrict__ bias, const float* __restrict__ v,
    float* __restrict__ scores) {
    constexpr int KC = K / KCH;     // 8 or 4
    constexpr int NT = N / 128;     // 6 or 4
    constexpr int NC = NT * KC;

    extern __shared__ char sm[];
    const uint32_t su = smem_u32(sm);
    float* sred = (float*)(sm + 3 * BUF_B);

    const int tid = threadIdx.x, lane = tid & 31, wid = tid >> 5;
    const int wm = wid & 3, wn = wid >> 2;
    const int b = blockIdx.y, s0 = blockIdx.x * 128;

    // cp.async: thread covers (row = tid/2, 32-elem half = tid&1); 4x16B each
    const int cr = tid >> 1, ch = tid & 1;
    const long abase = ((long)b * SS + min(s0 + cr, SS - 1)) * HH + ch * 32;
    const uint32_t cd = (uint32_t)((cr * TSTR + ch * 32) * 2);

    auto issue = [&](int c) {
        if (c < NC) {
            const int nt = c / KC, kc = c - nt * KC;
            const __half* asrc;
            int kofs;
            if (K == 512 && kc >= 4) { asrc = A16_d; kofs = (kc - 4) * KCH; }
            else                     { asrc = A16_s; kofs = kc * KCH; }
            const __half* pa = asrc + abase + kofs;
            const long wrow = (long)(nt * 128 + cr) * K + kc * KCH + ch * 32;
            const uint32_t d = su + (uint32_t)(c % 3) * BUF_B + cd;
#pragma unroll
            for (int q = 0; q < 4; q++) {
                cpa16(d + A_OFF + q * 16, pa + q * 8);
                cpa16(d + W_OFF + q * 16, Wh + wrow + q * 8);
            }
        }
    };

    // ldmatrix per-thread base offsets (bytes), within a buffer
    const uint32_t a_sm = (uint32_t)((wm * 32 + (lane & 15)) * (TSTR * 2) + ((lane >> 4) & 1) * 16);
    const uint32_t w_sm = (uint32_t)((wn * 64 + (lane & 7) + ((lane & 16) >> 1)) * (TSTR * 2) + (lane & 8) * 2);

    float part[4] = {0.f, 0.f, 0.f, 0.f};

    issue(0); CP_COMMIT();
    issue(1); CP_COMMIT();

    float acc[2][8][4];

    for (int c = 0; c < NC; c++) {
        const int kc = c % KC;
        const int nt = c / KC;
        if (kc == 0) {
#pragma unroll
            for (int i = 0; i < 2; i++)
#pragma unroll
                for (int j = 0; j < 8; j++)
#pragma unroll
                    for (int q = 0; q < 4; q++) acc[i][j][q] = 0.f;
        }

        CP_WAIT1();          // group c landed (group c+1 may be in flight)
        __syncthreads();     // all warps done reading buf (c-1)%3 + visibility
        issue(c + 2);        // refill buf (c+2)%3 == (c-1)%3
        CP_COMMIT();

        const uint32_t bo = su + (uint32_t)(c % 3) * BUF_B;
#pragma unroll
        for (int ks = 0; ks < 4; ks++) {
            const uint32_t ko = (uint32_t)(ks * 32);  // 16 elems * 2B
            uint32_t af[2][4];
#pragma unroll
            for (int mi = 0; mi < 2; mi++)
                ldm4(af[mi], bo + A_OFF + a_sm + (uint32_t)(mi * 16 * TSTR * 2) + ko);
#pragma unroll
            for (int ng = 0; ng < 4; ng++) {
                uint32_t wf[4];
                ldm4(wf, bo + W_OFF + w_sm + (uint32_t)(ng * 16 * TSTR * 2) + ko);
#pragma unroll
                for (int mi = 0; mi < 2; mi++) {
                    mma_f16(acc[mi][2 * ng],     af[mi], wf[0], wf[1]);
                    mma_f16(acc[mi][2 * ng + 1], af[mi], wf[2], wf[3]);
                }
            }
        }

        if (kc == KC - 1) {
            // ---- epilogue for this N tile: tanh + v-dot, register-only ----
            const int jb = nt * 128 + wn * 64 + 2 * (lane & 3);
#pragma unroll
            for (int n8 = 0; n8 < 8; n8++) {
                const int j = jb + n8 * 8;
                const float2 bv = *reinterpret_cast<const float2*>(&bias[(long)b * N + j]);
                const float2 vv = *reinterpret_cast<const float2*>(&v[j]);
#pragma unroll
                for (int mi = 0; mi < 2; mi++) {
                    part[mi * 2 + 0] += vv.x * tanha(acc[mi][n8][0] + bv.x)
                                      + vv.y * tanha(acc[mi][n8][1] + bv.y);
                    part[mi * 2 + 1] += vv.x * tanha(acc[mi][n8][2] + bv.x)
                                      + vv.y * tanha(acc[mi][n8][3] + bv.y);
                }
            }
        }
    }

    // reduce across the 4 lanes sharing a row (lane bits 0,1)
#pragma unroll
    for (int i = 0; i < 4; i++) {
        part[i] += __shfl_xor_sync(0xffffffffu, part[i], 1);
        part[i] += __shfl_xor_sync(0xffffffffu, part[i], 2);
    }
    if ((lane & 3) == 0) {
        const int r = lane >> 2;
        const int base = wn * 128 + wm * 32;
        sred[base + r]      = part[0];
        sred[base + r + 8]  = part[1];
        sred[base + r + 16] = part[2];
        sred[base + r + 24] = part[3];
    }
    __syncthreads();
    if (tid < 128) {
        const int s = s0 + tid;
        if (s < SS) scores[b * SP + s] = sred[tid] + sred[128 + tid];
    }
}

// ============================================================================
// Kernel 3: softmax(scores) -> context (fp16 static, all 256 threads) -> bias_dec
// ============================================================================
__global__ __launch_bounds__(256) void k_ctx(
    const __half* __restrict__ A16_s, const float* __restrict__ decW) {
    const int b = blockIdx.x;
    const int t = threadIdx.x;

    __shared__ float attn[SP];
    __shared__ float red[256];
    __shared__ __align__(16) float ctx[HH];
    __shared__ float ctx2[2][HH];

    float m = -1e30f;
    for (int s = t; s < SS; s += 256) m = fmaxf(m, g_scores[b * SP + s]);
    red[t] = m; __syncthreads();
    for (int o = 128; o; o >>= 1) { if (t < o) red[t] = fmaxf(red[t], red[t + o]); __syncthreads(); }
    m = red[0]; __syncthreads();

    float lsum = 0.f;
    for (int s = t; s < SS; s += 256) {
        const float e = __expf(g_scores[b * SP + s] - m);
        attn[s] = e; lsum += e;
    }
    red[t] = lsum; __syncthreads();
    for (int o = 128; o; o >>= 1) { if (t < o) red[t] += red[t + o]; __syncthreads(); }
    const float inv = 1.f / red[0];
    __syncthreads();

    // context with all 256 threads: tt = h-pair index, sh2 = s parity
    {
        const int tt = t & 127, sh2 = t >> 7;
        const __half2* sp = reinterpret_cast<const __half2*>(A16_s + (long)b * SS * HH) + tt;
        float c0 = 0.f, c1 = 0.f;
        for (int s = sh2; s < SS; s += 2) {
            const float2 v0 = __half22float2(sp[s * (HH / 2)]);
            c0 += attn[s] * v0.x;
            c1 += attn[s] * v0.y;
        }
        ctx2[sh2][2 * tt]     = c0;
        ctx2[sh2][2 * tt + 1] = c1;
    }
    __syncthreads();
    if (t < HH) ctx[t] = (ctx2[0][t] + ctx2[1][t]) * inv;
    __syncthreads();

    const float4* cv = reinterpret_cast<const float4*>(ctx);
#pragma unroll
    for (int g = 0; g < 2; g++) {
        const int j = g * HH + t;
        const float4* w = reinterpret_cast<const float4*>(decW + j * 512 + 256);
        float sacc = 0.f;
#pragma unroll 4
        for (int k = 0; k < HH / 4; k++) {
            float4 ww = w[k], cc = cv[k];
            sacc += ww.x * cc.x + ww.y * cc.y + ww.z * cc.z + ww.w * cc.w;
        }
        g_bias_dec[b * 512 + j] = sacc;
    }
}

// ============================================================================
// Kernel 5: final softmax -> outputs [B,S]
// ============================================================================
__global__ __launch_bounds__(256) void k_softmax_out(float* __restrict__ out) {
    const int b = blockIdx.x;
    const int t = threadIdx.x;
    __shared__ float e_s[SP];
    __shared__ float red[256];

    float m = -1e30f;
    for (int s = t; s < SS; s += 256) m = fmaxf(m, g_oscores[b * SP + s]);
    red[t] = m; __syncthreads();
    for (int o = 128; o; o >>= 1) { if (t < o) red[t] = fmaxf(red[t], red[t + o]); __syncthreads(); }
    m = red[0]; __syncthreads();

    float lsum = 0.f;
    for (int s = t; s < SS; s += 256) {
        const float e = __expf(g_oscores[b * SP + s] - m);
        e_s[s] = e; lsum += e;
    }
    red[t] = lsum; __syncthreads();
    for (int o = 128; o; o >>= 1) { if (t < o) red[t] += red[t + o]; __syncthreads(); }
    const float inv = 1.f / red[0];
    __syncthreads();

    for (int s = t; s < SS; s += 256) out[b * SS + s] = e_s[s] * inv;
}

// ============================================================================
// Launch
// ============================================================================
extern "C" void kernel_launch(void* const* d_in, const int* in_sizes, int n_in,
                              void* d_out, int out_size) {
    const float* din   = (const float*)d_in[0];
    const float* lasth = (const float*)d_in[1];
    const float* statp = (const float*)d_in[2];
    const float* dynp  = (const float*)d_in[3];
    const float* embW  = (const float*)d_in[4];
    const float* embb  = (const float*)d_in[5];
    const float* Wih   = (const float*)d_in[6];
    const float* Whh   = (const float*)d_in[7];
    const float* bih   = (const float*)d_in[8];
    const float* bhh   = (const float*)d_in[9];
    const float* attnW = (const float*)d_in[10];
    const float* attnv = (const float*)d_in[11];
    const float* decW  = (const float*)d_in[12];
    const float* decv  = (const float*)d_in[13];
    float* out = (float*)d_out;

    const int write_hidden = (out_size >= BB * SS + BB * HH) ? 1 : 0;
    float* hid_out = out + BB * SS;

    float *p_bias_attn, *p_scores, *p_bias_dec, *p_oscores;
    __half *pWh_a, *pWh_d, *pA16_s, *pA16_d;
    cudaGetSymbolAddress((void**)&p_bias_attn, g_bias_attn);
    cudaGetSymbolAddress((void**)&p_scores,    g_scores);
    cudaGetSymbolAddress((void**)&p_bias_dec,  g_bias_dec);
    cudaGetSymbolAddress((void**)&p_oscores,   g_oscores);
    cudaGetSymbolAddress((void**)&pWh_a, g_Wh_a);
    cudaGetSymbolAddress((void**)&pWh_d, g_Wh_d);
    cudaGetSymbolAddress((void**)&pA16_s, g_A16_s);
    cudaGetSymbolAddress((void**)&pA16_d, g_A16_d);

    cudaFuncSetAttribute(k_gemm<512, 768>, cudaFuncAttributeMaxDynamicSharedMemorySize, SMEM_GEMM);
    cudaFuncSetAttribute(k_gemm<256, 512>, cudaFuncAttributeMaxDynamicSharedMemorySize, SMEM_GEMM);

    k_prep<<<PREP_BLOCKS, 256>>>(attnW, decW, statp, dynp);

    k_gru<<<BB, 256>>>(din, lasth, embW, embb, Wih, Whh, bih, bhh, attnW,
                       hid_out, write_hidden);

    dim3 g(8, BB);  // 8 M-tiles of 128 rows, 128 batches
    k_gemm<512, 768><<<g, 256, SMEM_GEMM>>>(pA16_s, pA16_d,
                                            pWh_a, p_bias_attn, attnv, p_scores);

    k_ctx<<<BB, 256>>>(pA16_s, decW);

    k_gemm<256, 512><<<g, 256, SMEM_GEMM>>>(pA16_s, pA16_s,
                                            pWh_d, p_bias_dec, decv, p_oscores);

    k_softmax_out<<<BB, 256>>>(out);
}

// round 16
// speedup vs baseline: 1.0868x; 1.0531x over previous
#include <cuda_runtime.h>
#include <cuda_fp16.h>
#include <math.h>
#include <stdint.h>

// Shapes (fixed by the problem)
#define BB 128
#define SS 1000
#define HH 256
#define SP 1024
#define CPARTS 8
#define SSLICE (SS / CPARTS)   // 125

// ---------------- scratch (device globals; no allocations allowed) ----------
__device__ float g_bias_attn[BB * 768];
__device__ float g_scores[BB * SP];
__device__ float g_bias_dec[BB * 512];
__device__ float g_oscores[BB * SP];
__device__ float g_ctxp[BB * CPARTS * HH];   // partial contexts
// Weights as single fp16, K-packed rows
__device__ __half g_Wh_a[768 * 512];
__device__ __half g_Wh_d[512 * 256];
// Activations as single fp16: [b][s][k]
__device__ __half g_A16_s[BB * SS * HH];
__device__ __half g_A16_d[BB * SS * HH];

// ============================================================================
// Baseline-PTX helpers (compile under compute_103: mma.sync / ldmatrix / cp.async)
// ============================================================================
__device__ __forceinline__ uint32_t smem_u32(const void* p) {
    uint32_t a;
    asm("{ .reg .u64 t; cvta.to.shared.u64 t, %1; cvt.u32.u64 %0, t; }" : "=r"(a) : "l"(p));
    return a;
}
__device__ __forceinline__ void ldm4(uint32_t* r, uint32_t addr) {
    asm volatile("ldmatrix.sync.aligned.m8n8.x4.shared.b16 {%0,%1,%2,%3}, [%4];"
                 : "=r"(r[0]), "=r"(r[1]), "=r"(r[2]), "=r"(r[3]) : "r"(addr));
}
__device__ __forceinline__ void mma_f16(float* c, const uint32_t* a, uint32_t b0, uint32_t b1) {
    asm volatile("mma.sync.aligned.m16n8k16.row.col.f32.f16.f16.f32 "
                 "{%0,%1,%2,%3}, {%4,%5,%6,%7}, {%8,%9}, {%0,%1,%2,%3};"
                 : "+f"(c[0]), "+f"(c[1]), "+f"(c[2]), "+f"(c[3])
                 : "r"(a[0]), "r"(a[1]), "r"(a[2]), "r"(a[3]), "r"(b0), "r"(b1));
}
__device__ __forceinline__ void cpa16(uint32_t dst, const void* src) {
    asm volatile("cp.async.cg.shared.global [%0], [%1], 16;" :: "r"(dst), "l"(src));
}
#define CP_COMMIT() asm volatile("cp.async.commit_group;" ::: "memory")
#define CP_WAIT1()  asm volatile("cp.async.wait_group 1;" ::: "memory")
// MUFU-based tanh (sm_75+ baseline PTX), max err ~2^-10.66
__device__ __forceinline__ float tanha(float x) {
    float y;
    asm("tanh.approx.f32 %0, %1;" : "=f"(y) : "f"(x));
    return y;
}

// ============================================================================
// Kernel 0: fused weight+activation fp16 prep, FAT grid-stride blocks.
// ============================================================================
#define PREP_BLOCKS 2368

__global__ __launch_bounds__(256) void k_prep(
    const float* __restrict__ attnW, const float* __restrict__ decW,
    const float* __restrict__ statp, const float* __restrict__ dynp) {
    const long tid0 = (long)blockIdx.x * 256 + threadIdx.x;
    const long nthr = (long)PREP_BLOCKS * 256;

    const int WTOT = 768 * 512 + 512 * 256;
    for (long i = tid0; i < WTOT; i += nthr) {
        if (i < 768 * 512) {
            const int j = (int)(i >> 9), k = (int)(i & 511);
            g_Wh_a[i] = __float2half_rn(attnW[j * 768 + k]);
        } else {
            const int q = (int)(i - 768 * 512);
            const int j = q >> 8, k = q & 255;
            g_Wh_d[q] = __float2half_rn(decW[j * 512 + k]);
        }
    }

    const long E4 = (long)BB * SS * HH / 4;
    for (long i = tid0; i < 2 * E4; i += nthr) {
        const bool dyn = (i >= E4);
        const long j = dyn ? i - E4 : i;
        const float4 x = reinterpret_cast<const float4*>(dyn ? dynp : statp)[j];
        __half2 lo = __floats2half2_rn(x.x, x.y);
        __half2 hi = __floats2half2_rn(x.z, x.w);
        uint2* dst = reinterpret_cast<uint2*>(dyn ? g_A16_d : g_A16_s);
        dst[j] = make_uint2(*(const unsigned*)&lo, *(const unsigned*)&hi);
    }
}

// ============================================================================
// Kernel 1: embed + GRU cell + bias_attn  (fp32)
// ============================================================================
__global__ __launch_bounds__(256) void k_gru(
    const float* __restrict__ din, const float* __restrict__ lasth,
    const float* __restrict__ embW, const float* __restrict__ embb,
    const float* __restrict__ Wih, const float* __restrict__ Whh,
    const float* __restrict__ bih, const float* __restrict__ bhh,
    const float* __restrict__ attnW, float* __restrict__ hid_out, int write_hidden) {
    const int b = blockIdx.x;
    const int t = threadIdx.x;

    __shared__ __align__(16) float emb[HH];
    __shared__ __align__(16) float hold[HH];
    __shared__ __align__(16) float hnew[HH];

    const float d0 = din[b * 2 + 0];
    const float d1 = din[b * 2 + 1];
    emb[t]  = d0 * embW[t * 2 + 0] + d1 * embW[t * 2 + 1] + embb[t];
    hold[t] = lasth[b * HH + t];
    __syncthreads();

    float gx[3], gh[3];
#pragma unroll
    for (int g = 0; g < 3; g++) { gx[g] = bih[g * HH + t]; gh[g] = bhh[g * HH + t]; }
#pragma unroll
    for (int g = 0; g < 3; g++) {
        const float4* wi = reinterpret_cast<const float4*>(Wih + (g * HH + t) * HH);
        const float4* wh = reinterpret_cast<const float4*>(Whh + (g * HH + t) * HH);
        const float4* ev = reinterpret_cast<const float4*>(emb);
        const float4* hv = reinterpret_cast<const float4*>(hold);
        float sx = 0.f, sh = 0.f;
#pragma unroll 4
        for (int k = 0; k < HH / 4; k++) {
            float4 a = wi[k], c = wh[k], e = ev[k], h4 = hv[k];
            sx += a.x * e.x + a.y * e.y + a.z * e.z + a.w * e.w;
            sh += c.x * h4.x + c.y * h4.y + c.z * h4.z + c.w * h4.w;
        }
        gx[g] += sx; gh[g] += sh;
    }

    const float r = 1.f / (1.f + expf(-(gx[0] + gh[0])));
    const float z = 1.f / (1.f + expf(-(gx[1] + gh[1])));
    const float n = tanhf(gx[2] + r * gh[2]);
    const float hv = (1.f - z) * n + z * hold[t];
    hnew[t] = hv;
    if (write_hidden) hid_out[b * HH + t] = hv;
    __syncthreads();

    const float4* hv4 = reinterpret_cast<const float4*>(hnew);
#pragma unroll
    for (int g = 0; g < 3; g++) {
        const int j = g * HH + t;
        const float4* w = reinterpret_cast<const float4*>(attnW + j * 768 + 512);
        float s = 0.f;
#pragma unroll 4
        for (int k = 0; k < HH / 4; k++) {
            float4 ww = w[k], hh = hv4[k];
            s += ww.x * hh.x + ww.y * hh.y + ww.z * hh.z + ww.w * hh.w;
        }
        g_bias_attn[b * 768 + j] = s;
    }
}

// ============================================================================
// Kernel 2/4: fused score GEMM on HMMA (single fp16 term, fp32 accum)
// R12 config (best known).
// ============================================================================
#define KCH   64
#define TSTR  72
#define TILE_B (128 * TSTR * 2)   // 18432 bytes
#define A_OFF  0
#define W_OFF  TILE_B
#define BUF_B  (2 * TILE_B)       // 36864 bytes
#define SMEM_GEMM (3 * BUF_B + 1024)

template <int K, int N>
__global__ __launch_bounds__(256, 2) void k_gemm(
    const __half* __restrict__ A16_s, const __half* __restrict__ A16_d,
    const __half* __restrict__ Wh,
    const float* __restrict__ bias, const float* __restrict__ v,
    float* __restrict__ scores) {
    constexpr int KC = K / KCH;     // 8 or 4
    constexpr int NT = N / 128;     // 6 or 4
    constexpr int NC = NT * KC;

    extern __shared__ char sm[];
    const uint32_t su = smem_u32(sm);
    float* sred = (float*)(sm + 3 * BUF_B);

    const int tid = threadIdx.x, lane = tid & 31, wid = tid >> 5;
    const int wm = wid & 3, wn = wid >> 2;
    const int b = blockIdx.y, s0 = blockIdx.x * 128;

    const int cr = tid >> 1, ch = tid & 1;
    const long abase = ((long)b * SS + min(s0 + cr, SS - 1)) * HH + ch * 32;
    const uint32_t cd = (uint32_t)((cr * TSTR + ch * 32) * 2);

    auto issue = [&](int c) {
        if (c < NC) {
            const int nt = c / KC, kc = c - nt * KC;
            const __half* asrc;
            int kofs;
            if (K == 512 && kc >= 4) { asrc = A16_d; kofs = (kc - 4) * KCH; }
            else                     { asrc = A16_s; kofs = kc * KCH; }
            const __half* pa = asrc + abase + kofs;
            const long wrow = (long)(nt * 128 + cr) * K + kc * KCH + ch * 32;
            const uint32_t d = su + (uint32_t)(c % 3) * BUF_B + cd;
#pragma unroll
            for (int q = 0; q < 4; q++) {
                cpa16(d + A_OFF + q * 16, pa + q * 8);
                cpa16(d + W_OFF + q * 16, Wh + wrow + q * 8);
            }
        }
    };

    const uint32_t a_sm = (uint32_t)((wm * 32 + (lane & 15)) * (TSTR * 2) + ((lane >> 4) & 1) * 16);
    const uint32_t w_sm = (uint32_t)((wn * 64 + (lane & 7) + ((lane & 16) >> 1)) * (TSTR * 2) + (lane & 8) * 2);

    float part[4] = {0.f, 0.f, 0.f, 0.f};

    issue(0); CP_COMMIT();
    issue(1); CP_COMMIT();

    float acc[2][8][4];

    for (int c = 0; c < NC; c++) {
        const int kc = c % KC;
        const int nt = c / KC;
        if (kc == 0) {
#pragma unroll
            for (int i = 0; i < 2; i++)
#pragma unroll
                for (int j = 0; j < 8; j++)
#pragma unroll
                    for (int q = 0; q < 4; q++) acc[i][j][q] = 0.f;
        }

        CP_WAIT1();
        __syncthreads();
        issue(c + 2);
        CP_COMMIT();

        const uint32_t bo = su + (uint32_t)(c % 3) * BUF_B;
#pragma unroll
        for (int ks = 0; ks < 4; ks++) {
            const uint32_t ko = (uint32_t)(ks * 32);
            uint32_t af[2][4];
#pragma unroll
            for (int mi = 0; mi < 2; mi++)
                ldm4(af[mi], bo + A_OFF + a_sm + (uint32_t)(mi * 16 * TSTR * 2) + ko);
#pragma unroll
            for (int ng = 0; ng < 4; ng++) {
                uint32_t wf[4];
                ldm4(wf, bo + W_OFF + w_sm + (uint32_t)(ng * 16 * TSTR * 2) + ko);
#pragma unroll
                for (int mi = 0; mi < 2; mi++) {
                    mma_f16(acc[mi][2 * ng],     af[mi], wf[0], wf[1]);
                    mma_f16(acc[mi][2 * ng + 1], af[mi], wf[2], wf[3]);
                }
            }
        }

        if (kc == KC - 1) {
            const int jb = nt * 128 + wn * 64 + 2 * (lane & 3);
#pragma unroll
            for (int n8 = 0; n8 < 8; n8++) {
                const int j = jb + n8 * 8;
                const float2 bv = *reinterpret_cast<const float2*>(&bias[(long)b * N + j]);
                const float2 vv = *reinterpret_cast<const float2*>(&v[j]);
#pragma unroll
                for (int mi = 0; mi < 2; mi++) {
                    part[mi * 2 + 0] += vv.x * tanha(acc[mi][n8][0] + bv.x)
                                      + vv.y * tanha(acc[mi][n8][1] + bv.y);
                    part[mi * 2 + 1] += vv.x * tanha(acc[mi][n8][2] + bv.x)
                                      + vv.y * tanha(acc[mi][n8][3] + bv.y);
                }
            }
        }
    }

#pragma unroll
    for (int i = 0; i < 4; i++) {
        part[i] += __shfl_xor_sync(0xffffffffu, part[i], 1);
        part[i] += __shfl_xor_sync(0xffffffffu, part[i], 2);
    }
    if ((lane & 3) == 0) {
        const int r = lane >> 2;
        const int base = wn * 128 + wm * 32;
        sred[base + r]      = part[0];
        sred[base + r + 8]  = part[1];
        sred[base + r + 16] = part[2];
        sred[base + r + 24] = part[3];
    }
    __syncthreads();
    if (tid < 128) {
        const int s = s0 + tid;
        if (s < SS) scores[b * SP + s] = sred[tid] + sred[128 + tid];
    }
}

// ============================================================================
// Kernel 3a: softmax + PARTIAL context.  grid (BB, CPARTS).
// Each block redoes the cheap 1000-elem softmax reduction for its batch,
// then accumulates context over its own 125-s slice (x8 parallelism vs R15).
// Partial written to g_ctxp scaled by inv.
// ============================================================================
__global__ __launch_bounds__(256) void k_ctx_part(const __half* __restrict__ A16_s) {
    const int b = blockIdx.x;
    const int p = blockIdx.y;
    const int t = threadIdx.x;

    __shared__ float attn[SSLICE];     // only this block's slice
    __shared__ float red[256];

    // softmax stats over FULL S (cheap: 1000 loads)
    float m = -1e30f;
    for (int s = t; s < SS; s += 256) m = fmaxf(m, g_scores[b * SP + s]);
    red[t] = m; __syncthreads();
    for (int o = 128; o; o >>= 1) { if (t < o) red[t] = fmaxf(red[t], red[t + o]); __syncthreads(); }
    m = red[0]; __syncthreads();

    float lsum = 0.f;
    for (int s = t; s < SS; s += 256) lsum += __expf(g_scores[b * SP + s] - m);
    red[t] = lsum; __syncthreads();
    for (int o = 128; o; o >>= 1) { if (t < o) red[t] += red[t + o]; __syncthreads(); }
    const float inv = 1.f / red[0];
    __syncthreads();

    // this block's attn slice
    const int sbeg = p * SSLICE;
    for (int i = t; i < SSLICE; i += 256)
        attn[i] = __expf(g_scores[b * SP + sbeg + i] - m);
    __syncthreads();

    // partial context: 256 threads = 128 h-pairs x 2-way s split
    __shared__ float ctx2[2][HH];
    {
        const int tt = t & 127, sh2 = t >> 7;
        const __half2* sp = reinterpret_cast<const __half2*>(
            A16_s + ((long)b * SS + sbeg) * HH) + tt;
        float c0 = 0.f, c1 = 0.f;
        for (int i = sh2; i < SSLICE; i += 2) {
            const float2 v0 = __half22float2(sp[i * (HH / 2)]);
            c0 += attn[i] * v0.x;
            c1 += attn[i] * v0.y;
        }
        ctx2[sh2][2 * tt]     = c0;
        ctx2[sh2][2 * tt + 1] = c1;
    }
    __syncthreads();
    if (t < HH)
        g_ctxp[(b * CPARTS + p) * HH + t] = (ctx2[0][t] + ctx2[1][t]) * inv;
}

// ============================================================================
// Kernel 3b: combine partials (fixed order, deterministic) -> bias_dec
// ============================================================================
__global__ __launch_bounds__(256) void k_bias_dec(const float* __restrict__ decW) {
    const int b = blockIdx.x;
    const int t = threadIdx.x;

    __shared__ __align__(16) float ctx[HH];
    if (t < HH) {
        float c = 0.f;
#pragma unroll
        for (int p = 0; p < CPARTS; p++)
            c += g_ctxp[(b * CPARTS + p) * HH + t];
        ctx[t] = c;
    }
    __syncthreads();

    const float4* cv = reinterpret_cast<const float4*>(ctx);
#pragma unroll
    for (int g = 0; g < 2; g++) {
        const int j = g * HH + t;
        const float4* w = reinterpret_cast<const float4*>(decW + j * 512 + 256);
        float sacc = 0.f;
#pragma unroll 4
        for (int k = 0; k < HH / 4; k++) {
            float4 ww = w[k], cc = cv[k];
            sacc += ww.x * cc.x + ww.y * cc.y + ww.z * cc.z + ww.w * cc.w;
        }
        g_bias_dec[b * 512 + j] = sacc;
    }
}

// ============================================================================
// Kernel 5: final softmax -> outputs [B,S]
// ============================================================================
__global__ __launch_bounds__(256) void k_softmax_out(float* __restrict__ out) {
    const int b = blockIdx.x;
    const int t = threadIdx.x;
    __shared__ float e_s[SP];
    __shared__ float red[256];

    float m = -1e30f;
    for (int s = t; s < SS; s += 256) m = fmaxf(m, g_oscores[b * SP + s]);
    red[t] = m; __syncthreads();
    for (int o = 128; o; o >>= 1) { if (t < o) red[t] = fmaxf(red[t], red[t + o]); __syncthreads(); }
    m = red[0]; __syncthreads();

    float lsum = 0.f;
    for (int s = t; s < SS; s += 256) {
        const float e = __expf(g_oscores[b * SP + s] - m);
        e_s[s] = e; lsum += e;
    }
    red[t] = lsum; __syncthreads();
    for (int o = 128; o; o >>= 1) { if (t < o) red[t] += red[t + o]; __syncthreads(); }
    const float inv = 1.f / red[0];
    __syncthreads();

    for (int s = t; s < SS; s += 256) out[b * SS + s] = e_s[s] * inv;
}

// ============================================================================
// Launch
// ============================================================================
extern "C" void kernel_launch(void* const* d_in, const int* in_sizes, int n_in,
                              void* d_out, int out_size) {
    const float* din   = (const float*)d_in[0];
    const float* lasth = (const float*)d_in[1];
    const float* statp = (const float*)d_in[2];
    const float* dynp  = (const float*)d_in[3];
    const float* embW  = (const float*)d_in[4];
    const float* embb  = (const float*)d_in[5];
    const float* Wih   = (const float*)d_in[6];
    const float* Whh   = (const float*)d_in[7];
    const float* bih   = (const float*)d_in[8];
    const float* bhh   = (const float*)d_in[9];
    const float* attnW = (const float*)d_in[10];
    const float* attnv = (const float*)d_in[11];
    const float* decW  = (const float*)d_in[12];
    const float* decv  = (const float*)d_in[13];
    float* out = (float*)d_out;

    const int write_hidden = (out_size >= BB * SS + BB * HH) ? 1 : 0;
    float* hid_out = out + BB * SS;

    float *p_bias_attn, *p_scores, *p_bias_dec, *p_oscores;
    __half *pWh_a, *pWh_d, *pA16_s, *pA16_d;
    cudaGetSymbolAddress((void**)&p_bias_attn, g_bias_attn);
    cudaGetSymbolAddress((void**)&p_scores,    g_scores);
    cudaGetSymbolAddress((void**)&p_bias_dec,  g_bias_dec);
    cudaGetSymbolAddress((void**)&p_oscores,   g_oscores);
    cudaGetSymbolAddress((void**)&pWh_a, g_Wh_a);
    cudaGetSymbolAddress((void**)&pWh_d, g_Wh_d);
    cudaGetSymbolAddress((void**)&pA16_s, g_A16_s);
    cudaGetSymbolAddress((void**)&pA16_d, g_A16_d);

    cudaFuncSetAttribute(k_gemm<512, 768>, cudaFuncAttributeMaxDynamicSharedMemorySize, SMEM_GEMM);
    cudaFuncSetAttribute(k_gemm<256, 512>, cudaFuncAttributeMaxDynamicSharedMemorySize, SMEM_GEMM);

    k_prep<<<PREP_BLOCKS, 256>>>(attnW, decW, statp, dynp);

    k_gru<<<BB, 256>>>(din, lasth, embW, embb, Wih, Whh, bih, bhh, attnW,
                       hid_out, write_hidden);

    dim3 g(8, BB);  // 8 M-tiles of 128 rows, 128 batches
    k_gemm<512, 768><<<g, 256, SMEM_GEMM>>>(pA16_s, pA16_d,
                                            pWh_a, p_bias_attn, attnv, p_scores);

    dim3 gc(BB, CPARTS);
    k_ctx_part<<<gc, 256>>>(pA16_s);
    k_bias_dec<<<BB, 256>>>(decW);

    k_gemm<256, 512><<<g, 256, SMEM_GEMM>>>(pA16_s, pA16_s,
                                            pWh_d, p_bias_dec, decv, p_oscores);

    k_softmax_out<<<BB, 256>>>(out);
}